// round 9
// baseline (speedup 1.0000x reference)
#include <cuda_runtime.h>

// Problem constants
#define Bx 8
#define Lx 256
#define Dx 256
#define BLD (Bx*Lx*Dx)   // 524288
#define BLL (Bx*Lx*Lx)   // 524288

typedef unsigned int u32;
typedef unsigned long long u64;

// Scratch (device globals — no allocation allowed)
__device__ float g_A[BLD],  g_Bm[BLD],  g_H[BLD];    // K-half 0 partials
__device__ float g_A2[BLD], g_Bm2[BLD], g_H2[BLD];   // K-half 1 partials
__device__ float g_W[BLL];                            // softmax weights

// ---- tf32 mma helpers ------------------------------------------------------
// NOTE: we feed RAW fp32 bits; HMMA.TF32 ignores the low mantissa bits
// (truncation instead of cvt.rna) — saves all alu-pipe cvts.
__device__ __forceinline__ void mma_tf32(float c[4], const u32 a[4], const u32 b[2]) {
    asm volatile(
        "mma.sync.aligned.m16n8k8.row.col.f32.tf32.tf32.f32 "
        "{%0,%1,%2,%3},{%4,%5,%6,%7},{%8,%9},{%0,%1,%2,%3};"
        : "+f"(c[0]), "+f"(c[1]), "+f"(c[2]), "+f"(c[3])
        : "r"(a[0]), "r"(a[1]), "r"(a[2]), "r"(a[3]), "r"(b[0]), "r"(b[1]));
}

// ---- packed f32x2 helpers (edge kernel) ------------------------------------
__device__ __forceinline__ u64 pack2(float lo, float hi) {
    u64 r; asm("mov.b64 %0,{%1,%2};" : "=l"(r) : "f"(lo), "f"(hi)); return r;
}
__device__ __forceinline__ void unpack2(u64 v, float& lo, float& hi) {
    asm("mov.b64 {%0,%1},%2;" : "=f"(lo), "=f"(hi) : "l"(v));
}
__device__ __forceinline__ u64 ffma2(u64 a, u64 b, u64 c) {
    u64 d; asm("fma.rn.f32x2 %0,%1,%2,%3;" : "=l"(d) : "l"(a), "l"(b), "l"(c)); return d;
}
__device__ __forceinline__ u64 fadd2(u64 a, u64 b) {
    u64 d; asm("add.rn.f32x2 %0,%1,%2;" : "=l"(d) : "l"(a), "l"(b)); return d;
}
__device__ __forceinline__ u64 fmax2z(u64 a) {
    float lo, hi; unpack2(a, lo, hi);
    return pack2(fmaxf(lo, 0.f), fmaxf(hi, 0.f));
}

// ---------------------------------------------------------------------------
// Kernel 1: projections via tf32 HMMA, K-split x2.
// C[m,n] = sum_k X[m,k]*W[n,k] (NT). Block 64m x 64n, 256 thr = 8 warps
// (2m x 4n), warp tile 32x16. grid (32, 4, 6): z>>1 = matrix, z&1 = K-half.
// 768 blocks -> ~5 blocks/SM. Consumers fuse the partial add.
// ---------------------------------------------------------------------------
__global__ __launch_bounds__(256) void proj_kernel(
    const float* __restrict__ Q,
    const float* __restrict__ Wa,
    const float* __restrict__ Wb,
    const float* __restrict__ Wd)
{
    int mat = blockIdx.z >> 1;
    int kh  = blockIdx.z & 1;
    const float* W = (mat == 0) ? Wa : (mat == 1) ? Wb : Wd;
    float* Out = (mat == 0) ? (kh ? g_A2 : g_A)
               : (mat == 1) ? (kh ? g_Bm2 : g_Bm)
                            : (kh ? g_H2 : g_H);

    __shared__ u32 Xs[2][16][136];   // [k][m], 64 m
    __shared__ u32 Ws[2][16][72];    // [k][n], 64 n

    int tid  = threadIdx.x;
    int m0 = blockIdx.x * 64, n0 = blockIdx.y * 64;
    int wid = tid >> 5, lane = tid & 31;
    int wm = wid & 1;        // 2 m-halves of 32
    int wn = wid >> 1;       // 4 n-quarters of 16
    int lg = lane >> 2, lk = lane & 3;

    int sr  = tid & 63;          // staging row (m or n)
    int sk4 = (tid >> 6) * 4;    // staging k base (0,4,8,12)
    int kbase = kh * 128;

    const float* xg = Q + (m0 + sr) * Dx + kbase + sk4;
    const float* wg = W + (n0 + sr) * Dx + kbase + sk4;

    float4 xv = *(const float4*)xg;
    float4 wv = *(const float4*)wg;
    Xs[0][sk4 + 0][sr] = __float_as_uint(xv.x); Xs[0][sk4 + 1][sr] = __float_as_uint(xv.y);
    Xs[0][sk4 + 2][sr] = __float_as_uint(xv.z); Xs[0][sk4 + 3][sr] = __float_as_uint(xv.w);
    Ws[0][sk4 + 0][sr] = __float_as_uint(wv.x); Ws[0][sk4 + 1][sr] = __float_as_uint(wv.y);
    Ws[0][sk4 + 2][sr] = __float_as_uint(wv.z); Ws[0][sk4 + 3][sr] = __float_as_uint(wv.w);
    __syncthreads();

    float c[2][2][4];   // [mt][nt][frag]
#pragma unroll
    for (int mt = 0; mt < 2; mt++)
#pragma unroll
        for (int nt = 0; nt < 2; nt++)
#pragma unroll
            for (int q = 0; q < 4; q++) c[mt][nt][q] = 0.f;

#pragma unroll 1
    for (int it = 0; it < 8; it++) {
        int buf = it & 1;
        if (it < 7) {
            xv = *(const float4*)(xg + (it + 1) * 16);
            wv = *(const float4*)(wg + (it + 1) * 16);
        }
#pragma unroll
        for (int ks = 0; ks < 2; ks++) {
            int kc = ks * 8;
            u32 a[2][4], bfr[2][2];
#pragma unroll
            for (int mt = 0; mt < 2; mt++) {
                int mb = wm * 32 + mt * 16;
                a[mt][0] = Xs[buf][kc + lk][mb + lg];
                a[mt][1] = Xs[buf][kc + lk][mb + lg + 8];
                a[mt][2] = Xs[buf][kc + 4 + lk][mb + lg];
                a[mt][3] = Xs[buf][kc + 4 + lk][mb + lg + 8];
            }
#pragma unroll
            for (int nt = 0; nt < 2; nt++) {
                int nb = wn * 16 + nt * 8;
                bfr[nt][0] = Ws[buf][kc + lk][nb + lg];
                bfr[nt][1] = Ws[buf][kc + 4 + lk][nb + lg];
            }
#pragma unroll
            for (int mt = 0; mt < 2; mt++)
#pragma unroll
                for (int nt = 0; nt < 2; nt++)
                    mma_tf32(c[mt][nt], a[mt], bfr[nt]);
        }
        if (it < 7) {
            int nb = buf ^ 1;
            Xs[nb][sk4 + 0][sr] = __float_as_uint(xv.x); Xs[nb][sk4 + 1][sr] = __float_as_uint(xv.y);
            Xs[nb][sk4 + 2][sr] = __float_as_uint(xv.z); Xs[nb][sk4 + 3][sr] = __float_as_uint(xv.w);
            Ws[nb][sk4 + 0][sr] = __float_as_uint(wv.x); Ws[nb][sk4 + 1][sr] = __float_as_uint(wv.y);
            Ws[nb][sk4 + 2][sr] = __float_as_uint(wv.z); Ws[nb][sk4 + 3][sr] = __float_as_uint(wv.w);
            __syncthreads();
        }
    }

#pragma unroll
    for (int mt = 0; mt < 2; mt++) {
        int row = m0 + wm * 32 + mt * 16 + lg;
#pragma unroll
        for (int nt = 0; nt < 2; nt++) {
            int col = n0 + wn * 16 + nt * 8 + 2 * lk;
            *(float2*)(Out + row * Dx + col)       = make_float2(c[mt][nt][0], c[mt][nt][1]);
            *(float2*)(Out + (row + 8) * Dx + col) = make_float2(c[mt][nt][2], c[mt][nt][3]);
        }
    }
}

// ---------------------------------------------------------------------------
// Kernel 2: edge scores + mask + softmax -> g_W, tail casts folded in.
// Fuses the K-split partial adds: A = A1+A2, Bm = Bm1+Bm2 during staging.
// Block = (b, 8 rows), 256 threads = 8 warps; warp = (j-half, row-pair).
// ---------------------------------------------------------------------------
__global__ __launch_bounds__(256) void edge_kernel(
    const int* __restrict__ dep,
    const float* __restrict__ w2,
    const int* __restrict__ wl,
    float* __restrict__ dst)   // out + BLD, or nullptr
{
    int b  = blockIdx.y;
    int i0 = blockIdx.x * 8;

    __shared__ __align__(16) float Ash2[8][520];
    __shared__ __align__(16) float w2d[512];
    __shared__ __align__(16) float Bt[2][16][258];
    __shared__ float redmx[2][8], redsum[2][8];

    int tid = threadIdx.x;

#pragma unroll
    for (int p = 0; p < 2; p++) {
        int e = tid * 4 + p * 1024;
        int il = e >> 8, cc = e & 255;
        long off = (long)(b * Lx + i0 + il) * Dx + cc;
        float4 v1 = *(const float4*)(g_A + off);
        float4 v2 = *(const float4*)(g_A2 + off);
        float4 v = make_float4(v1.x + v2.x, v1.y + v2.y, v1.z + v2.z, v1.w + v2.w);
        *(u64*)&Ash2[il][2 * cc]     = pack2(v.x, v.x);
        *(u64*)&Ash2[il][2 * cc + 2] = pack2(v.y, v.y);
        *(u64*)&Ash2[il][2 * cc + 4] = pack2(v.z, v.z);
        *(u64*)&Ash2[il][2 * cc + 6] = pack2(v.w, v.w);
    }
    {
        float v = w2[tid];
        *(u64*)&w2d[2 * tid] = pack2(v, v);
    }
    if (dst && blockIdx.x == 0 && blockIdx.y == 0 && tid < Bx)
        dst[tid] = (float)wl[tid];
    float* depout = dst ? dst + Bx : nullptr;

    const float* B1 = g_Bm  + b * Lx * Dx;
    const float* B2 = g_Bm2 + b * Lx * Dx;

    float4 pf[4];
#pragma unroll
    for (int p = 0; p < 4; p++) {
        int e = tid * 4 + p * 1024;
        int j = e >> 4, cl = e & 15;
        float4 u1 = *(const float4*)(B1 + j * Dx + cl);
        float4 u2 = *(const float4*)(B2 + j * Dx + cl);
        pf[p] = make_float4(u1.x + u2.x, u1.y + u2.y, u1.z + u2.z, u1.w + u2.w);
    }
#pragma unroll
    for (int p = 0; p < 4; p++) {
        int e = tid * 4 + p * 1024;
        int j = e >> 4, cl = e & 15;
        Bt[0][cl + 0][j] = pf[p].x; Bt[0][cl + 1][j] = pf[p].y;
        Bt[0][cl + 2][j] = pf[p].z; Bt[0][cl + 3][j] = pf[p].w;
    }
    __syncthreads();

    int w  = tid >> 5;
    int jl = tid & 31;
    int jh = w >> 2;
    int wr = w & 3;
    int r0 = wr * 2, r1 = r0 + 1;
    int jbase = jh * 128;

    u64 acc0[2] = {0, 0}, acc1[2] = {0, 0};

#pragma unroll 1
    for (int ch = 0; ch < 16; ch++) {
        int buf = ch & 1;
        if (ch < 15) {
            int c0 = (ch + 1) * 16;
#pragma unroll
            for (int p = 0; p < 4; p++) {
                int e = tid * 4 + p * 1024;
                int j = e >> 4, cl = e & 15;
                float4 u1 = *(const float4*)(B1 + j * Dx + c0 + cl);
                float4 u2 = *(const float4*)(B2 + j * Dx + c0 + cl);
                pf[p] = make_float4(u1.x + u2.x, u1.y + u2.y, u1.z + u2.z, u1.w + u2.w);
            }
        }
#pragma unroll
        for (int c2 = 0; c2 < 8; c2++) {
            int cbase = ch * 16 + c2 * 2;
            ulonglong2 A0 = *(const ulonglong2*)&Ash2[r0][cbase * 2];
            ulonglong2 A1 = *(const ulonglong2*)&Ash2[r1][cbase * 2];
            ulonglong2 UU = *(const ulonglong2*)&w2d[cbase * 2];
#pragma unroll
            for (int cc = 0; cc < 2; cc++) {
                u64 a0 = cc ? A0.y : A0.x;
                u64 a1 = cc ? A1.y : A1.x;
                u64 up = cc ? UU.y : UU.x;
                int cl = c2 * 2 + cc;
#pragma unroll
                for (int gp = 0; gp < 2; gp++) {
                    u64 bt = *(const u64*)&Bt[buf][cl][jbase + gp * 64 + jl * 2];
                    acc0[gp] = ffma2(fmax2z(fadd2(a0, bt)), up, acc0[gp]);
                    acc1[gp] = ffma2(fmax2z(fadd2(a1, bt)), up, acc1[gp]);
                }
            }
        }
        if (ch < 15) {
            int nb = buf ^ 1;
#pragma unroll
            for (int p = 0; p < 4; p++) {
                int e = tid * 4 + p * 1024;
                int j = e >> 4, cl = e & 15;
                Bt[nb][cl + 0][j] = pf[p].x; Bt[nb][cl + 1][j] = pf[p].y;
                Bt[nb][cl + 2][j] = pf[p].z; Bt[nb][cl + 3][j] = pf[p].w;
            }
            __syncthreads();
        }
    }

    int gi0 = b * Lx + i0 + r0;
    int gi1 = b * Lx + i0 + r1;
    float T0[4], T1[4];
    int   mk0[4], mk1[4];
    float mx0 = -1e30f, mx1 = -1e30f;
#pragma unroll
    for (int gp = 0; gp < 2; gp++) {
        int j0 = jbase + gp * 64 + jl * 2;
        int2 m0v = *(const int2*)(dep + gi0 * Lx + j0);
        int2 m1v = *(const int2*)(dep + gi1 * Lx + j0);
        float lo, hi;
        unpack2(acc0[gp], lo, hi);
        mk0[2*gp]   = (m0v.x > 0);
        mk0[2*gp+1] = (m0v.y > 0);
        T0[2*gp]    = mk0[2*gp]   ? lo : -100.0f;
        T0[2*gp+1]  = mk0[2*gp+1] ? hi : -100.0f;
        unpack2(acc1[gp], lo, hi);
        mk1[2*gp]   = (m1v.x > 0);
        mk1[2*gp+1] = (m1v.y > 0);
        T1[2*gp]    = mk1[2*gp]   ? lo : -100.0f;
        T1[2*gp+1]  = mk1[2*gp+1] ? hi : -100.0f;
        mx0 = fmaxf(mx0, fmaxf(T0[2*gp], T0[2*gp+1]));
        mx1 = fmaxf(mx1, fmaxf(T1[2*gp], T1[2*gp+1]));
        if (depout) {
            *(float2*)(depout + gi0 * Lx + j0) = make_float2((float)m0v.x, (float)m0v.y);
            *(float2*)(depout + gi1 * Lx + j0) = make_float2((float)m1v.x, (float)m1v.y);
        }
    }
#pragma unroll
    for (int off = 16; off > 0; off >>= 1) {
        mx0 = fmaxf(mx0, __shfl_xor_sync(0xffffffffu, mx0, off));
        mx1 = fmaxf(mx1, __shfl_xor_sync(0xffffffffu, mx1, off));
    }
    if (jl == 0) { redmx[jh][r0] = mx0; redmx[jh][r1] = mx1; }
    __syncthreads();
    float gmx0 = fmaxf(redmx[0][r0], redmx[1][r0]);
    float gmx1 = fmaxf(redmx[0][r1], redmx[1][r1]);

    float E0[4], E1[4], sum0 = 0.f, sum1 = 0.f;
#pragma unroll
    for (int g = 0; g < 4; g++) {
        E0[g] = expf(T0[g] - gmx0); sum0 += E0[g];
        E1[g] = expf(T1[g] - gmx1); sum1 += E1[g];
    }
#pragma unroll
    for (int off = 16; off > 0; off >>= 1) {
        sum0 += __shfl_xor_sync(0xffffffffu, sum0, off);
        sum1 += __shfl_xor_sync(0xffffffffu, sum1, off);
    }
    if (jl == 0) { redsum[jh][r0] = sum0; redsum[jh][r1] = sum1; }
    __syncthreads();
    float inv0 = 1.0f / (redsum[0][r0] + redsum[1][r0]);
    float inv1 = 1.0f / (redsum[0][r1] + redsum[1][r1]);

#pragma unroll
    for (int gp = 0; gp < 2; gp++) {
        int j0 = jbase + gp * 64 + jl * 2;
        float2 o0, o1;
        o0.x = mk0[2*gp]   ? E0[2*gp]   * inv0 : 0.f;
        o0.y = mk0[2*gp+1] ? E0[2*gp+1] * inv0 : 0.f;
        o1.x = mk1[2*gp]   ? E1[2*gp]   * inv1 : 0.f;
        o1.y = mk1[2*gp+1] ? E1[2*gp+1] * inv1 : 0.f;
        *(float2*)(g_W + gi0 * Lx + j0) = o0;
        *(float2*)(g_W + gi1 * Lx + j0) = o1;
    }
}

// ---------------------------------------------------------------------------
// Kernel 3: agg via tf32 HMMA + fused epilogue. out = relu(Q + w@(H1+H2)).
// Block 32i x 64c, 256 thr = 8 warps (2m16 x 4n16), warp tile 16x16.
// grid (8, 4, 8) = 256 blocks.
// ---------------------------------------------------------------------------
__global__ __launch_bounds__(256) void agg_kernel(
    const float* __restrict__ Q,
    float* __restrict__ out)
{
    int b  = blockIdx.z;
    int i0 = blockIdx.x * 32;
    int c0 = blockIdx.y * 64;

    __shared__ u32 Wt[2][16][40];   // [j][i], 32 i
    __shared__ u32 Hs[2][64][20];   // [c][j], 16 j

    int tid = threadIdx.x;
    int wid = tid >> 5, lane = tid & 31;
    int wm = wid & 1;
    int wn = wid >> 1;
    int lg = lane >> 2, lk = lane & 3;

    int si  = tid & 31;
    int sj2 = (tid >> 5) * 2;
    int hj  = tid & 15;
    int hc4 = (tid >> 4) * 4;

    const float* Wg = g_W + (b * Lx + i0 + si) * Lx + sj2;
    const float* H1 = g_H  + (b * Lx + hj) * Dx + c0 + hc4;
    const float* H2 = g_H2 + (b * Lx + hj) * Dx + c0 + hc4;

    float2 wv = *(const float2*)Wg;
    float4 h1 = *(const float4*)H1;
    float4 h2 = *(const float4*)H2;
    float4 hv = make_float4(h1.x + h2.x, h1.y + h2.y, h1.z + h2.z, h1.w + h2.w);
    Wt[0][sj2][si]     = __float_as_uint(wv.x);
    Wt[0][sj2 + 1][si] = __float_as_uint(wv.y);
    Hs[0][hc4 + 0][hj] = __float_as_uint(hv.x); Hs[0][hc4 + 1][hj] = __float_as_uint(hv.y);
    Hs[0][hc4 + 2][hj] = __float_as_uint(hv.z); Hs[0][hc4 + 3][hj] = __float_as_uint(hv.w);
    __syncthreads();

    float c[2][4];
#pragma unroll
    for (int nt = 0; nt < 2; nt++)
#pragma unroll
        for (int q = 0; q < 4; q++) c[nt][q] = 0.f;

#pragma unroll 1
    for (int it = 0; it < 16; it++) {
        int buf = it & 1;
        if (it < 15) {
            wv = *(const float2*)(Wg + (it + 1) * 16);
            h1 = *(const float4*)(H1 + (it + 1) * 16 * Dx);
            h2 = *(const float4*)(H2 + (it + 1) * 16 * Dx);
            hv = make_float4(h1.x + h2.x, h1.y + h2.y, h1.z + h2.z, h1.w + h2.w);
        }
#pragma unroll
        for (int ks = 0; ks < 2; ks++) {
            int kc = ks * 8;
            u32 a[4], bfr[2][2];
            int mb = wm * 16;
            a[0] = Wt[buf][kc + lk][mb + lg];
            a[1] = Wt[buf][kc + lk][mb + lg + 8];
            a[2] = Wt[buf][kc + 4 + lk][mb + lg];
            a[3] = Wt[buf][kc + 4 + lk][mb + lg + 8];
#pragma unroll
            for (int nt = 0; nt < 2; nt++) {
                int cb = wn * 16 + nt * 8;
                bfr[nt][0] = Hs[buf][cb + lg][kc + lk];
                bfr[nt][1] = Hs[buf][cb + lg][kc + 4 + lk];
            }
#pragma unroll
            for (int nt = 0; nt < 2; nt++)
                mma_tf32(c[nt], a, bfr[nt]);
        }
        if (it < 15) {
            int nb = buf ^ 1;
            Wt[nb][sj2][si]     = __float_as_uint(wv.x);
            Wt[nb][sj2 + 1][si] = __float_as_uint(wv.y);
            Hs[nb][hc4 + 0][hj] = __float_as_uint(hv.x); Hs[nb][hc4 + 1][hj] = __float_as_uint(hv.y);
            Hs[nb][hc4 + 2][hj] = __float_as_uint(hv.z); Hs[nb][hc4 + 3][hj] = __float_as_uint(hv.w);
            __syncthreads();
        }
    }

#pragma unroll
    for (int nt = 0; nt < 2; nt++) {
        int col  = c0 + wn * 16 + nt * 8 + 2 * lk;
        int row0 = i0 + wm * 16 + lg;
        long base0 = (long)(b * Lx + row0) * Dx + col;
        long base1 = (long)(b * Lx + row0 + 8) * Dx + col;
        float2 q0 = *(const float2*)(Q + base0);
        float2 q1 = *(const float2*)(Q + base1);
        *(float2*)(out + base0) = make_float2(fmaxf(q0.x + c[nt][0], 0.f),
                                              fmaxf(q0.y + c[nt][1], 0.f));
        *(float2*)(out + base1) = make_float2(fmaxf(q1.x + c[nt][2], 0.f),
                                              fmaxf(q1.y + c[nt][3], 0.f));
    }
}

// ---------------------------------------------------------------------------
extern "C" void kernel_launch(void* const* d_in, const int* in_sizes, int n_in,
                              void* d_out, int out_size)
{
    const float* Q   = (const float*)d_in[0];
    const int*   wl  = (const int*)d_in[1];
    const int*   dep = (const int*)d_in[2];
    const float* Wa  = (const float*)d_in[3];
    const float* Wb  = (const float*)d_in[4];
    const float* w2  = (const float*)d_in[5];
    const float* Wd  = (const float*)d_in[6];
    float* out = (float*)d_out;

    float* dst = (out_size >= BLD + Bx + BLL) ? out + BLD : nullptr;

    // projections via tf32 HMMA, K-split x2 (768 blocks x 256 thr)
    proj_kernel<<<dim3(32, 4, 6), 256>>>(Q, Wa, Wb, Wd);
    // edge scores + softmax -> g_W (+ partial adds + tail casts)
    edge_kernel<<<dim3(32, Bx), 256>>>(dep, w2, wl, dst);
    // aggregation via tf32 HMMA + fused partial add + residual relu
    agg_kernel<<<dim3(8, 4, Bx), 256>>>(Q, out);
}

// round 11
// speedup vs baseline: 1.3650x; 1.3650x over previous
#include <cuda_runtime.h>
#include <cuda_fp16.h>

// Problem constants
#define Bx 8
#define Lx 256
#define Dx 256
#define BLD (Bx*Lx*Dx)   // 524288
#define BLL (Bx*Lx*Lx)   // 524288

typedef unsigned int u32;
typedef unsigned long long u64;

// Scratch (device globals — no allocation allowed)
__device__ float g_A[BLD], g_Bm[BLD], g_H[BLD];
__device__ float g_W[BLL];

// ---- fp16 m16n8k16 mma (fp32 accum) ---------------------------------------
__device__ __forceinline__ void mma_f16(float c[4], const u32 a[4], const u32 b[2]) {
    asm volatile(
        "mma.sync.aligned.m16n8k16.row.col.f32.f16.f16.f32 "
        "{%0,%1,%2,%3},{%4,%5,%6,%7},{%8,%9},{%0,%1,%2,%3};"
        : "+f"(c[0]), "+f"(c[1]), "+f"(c[2]), "+f"(c[3])
        : "r"(a[0]), "r"(a[1]), "r"(a[2]), "r"(a[3]), "r"(b[0]), "r"(b[1]));
}
__device__ __forceinline__ u32 h2u(float x, float y) {
    __half2 h = __floats2half2_rn(x, y);
    return *reinterpret_cast<u32*>(&h);
}

// ---- packed f32x2 helpers (edge kernel) ------------------------------------
__device__ __forceinline__ u64 pack2(float lo, float hi) {
    u64 r; asm("mov.b64 %0,{%1,%2};" : "=l"(r) : "f"(lo), "f"(hi)); return r;
}
__device__ __forceinline__ void unpack2(u64 v, float& lo, float& hi) {
    asm("mov.b64 {%0,%1},%2;" : "=f"(lo), "=f"(hi) : "l"(v));
}
__device__ __forceinline__ u64 ffma2(u64 a, u64 b, u64 c) {
    u64 d; asm("fma.rn.f32x2 %0,%1,%2,%3;" : "=l"(d) : "l"(a), "l"(b), "l"(c)); return d;
}
__device__ __forceinline__ u64 fadd2(u64 a, u64 b) {
    u64 d; asm("add.rn.f32x2 %0,%1,%2;" : "=l"(d) : "l"(a), "l"(b)); return d;
}
__device__ __forceinline__ u64 fmax2z(u64 a) {
    float lo, hi; unpack2(a, lo, hi);
    return pack2(fmaxf(lo, 0.f), fmaxf(hi, 0.f));
}

// ---------------------------------------------------------------------------
// Kernel 1: projections via fp16 HMMA m16n8k16. C[m,n]=sum_k X[m,k]W[n,k] (NT).
// Block 64m x 64n, 256 thr = 8 warps (2m32 x 4n16), warp tile 32x16.
// Xh/Wh: packed k-pair u32 rows [kp][row], stride 72 (== 8 mod 32 ->
// fragment loads conflict-free). 12 LDS.32 + 4 HMMA per iter per warp.
// grid (32, 4, 3) = 384 blocks.
// ---------------------------------------------------------------------------
__global__ __launch_bounds__(256) void proj_kernel(
    const float* __restrict__ Q,
    const float* __restrict__ Wa,
    const float* __restrict__ Wb,
    const float* __restrict__ Wd)
{
    int mat = blockIdx.z;
    const float* W = (mat == 0) ? Wa : (mat == 1) ? Wb : Wd;
    float* Out     = (mat == 0) ? g_A : (mat == 1) ? g_Bm : g_H;

    __shared__ u32 Xh[2][8][72];   // [kp][m], packed (k, k+1) fp16
    __shared__ u32 Wh[2][8][72];   // [kp][n]

    int tid  = threadIdx.x;
    int m0 = blockIdx.x * 64, n0 = blockIdx.y * 64;
    int wid = tid >> 5, lane = tid & 31;
    int wm = wid & 1;        // 2 m-halves of 32
    int wn = wid >> 1;       // 4 n-quarters of 16
    int lg = lane >> 2, lk = lane & 3;

    int sr  = tid & 63;          // staging row (m or n)
    int sk4 = (tid >> 6) * 4;    // staging k base (0,4,8,12)
    int kp0 = sk4 >> 1;          // 0,2,4,6

    const float* xg = Q + (m0 + sr) * Dx + sk4;
    const float* wg = W + (n0 + sr) * Dx + sk4;

    float4 xv = *(const float4*)xg;
    float4 wv = *(const float4*)wg;
    Xh[0][kp0][sr]     = h2u(xv.x, xv.y);
    Xh[0][kp0 + 1][sr] = h2u(xv.z, xv.w);
    Wh[0][kp0][sr]     = h2u(wv.x, wv.y);
    Wh[0][kp0 + 1][sr] = h2u(wv.z, wv.w);
    __syncthreads();

    float c[2][2][4];   // [mt][nt][frag]
#pragma unroll
    for (int mt = 0; mt < 2; mt++)
#pragma unroll
        for (int nt = 0; nt < 2; nt++)
#pragma unroll
            for (int q = 0; q < 4; q++) c[mt][nt][q] = 0.f;

#pragma unroll 1
    for (int it = 0; it < 16; it++) {
        int buf = it & 1;
        if (it < 15) {
            xv = *(const float4*)(xg + (it + 1) * 16);
            wv = *(const float4*)(wg + (it + 1) * 16);
        }
        u32 a[2][4], bfr[2][2];
#pragma unroll
        for (int mt = 0; mt < 2; mt++) {
            int mb = wm * 32 + mt * 16;
            a[mt][0] = Xh[buf][lk][mb + lg];
            a[mt][1] = Xh[buf][lk][mb + lg + 8];
            a[mt][2] = Xh[buf][lk + 4][mb + lg];
            a[mt][3] = Xh[buf][lk + 4][mb + lg + 8];
        }
#pragma unroll
        for (int nt = 0; nt < 2; nt++) {
            int nb = wn * 16 + nt * 8;
            bfr[nt][0] = Wh[buf][lk][nb + lg];
            bfr[nt][1] = Wh[buf][lk + 4][nb + lg];
        }
#pragma unroll
        for (int mt = 0; mt < 2; mt++)
#pragma unroll
            for (int nt = 0; nt < 2; nt++)
                mma_f16(c[mt][nt], a[mt], bfr[nt]);

        if (it < 15) {
            int nb = buf ^ 1;
            Xh[nb][kp0][sr]     = h2u(xv.x, xv.y);
            Xh[nb][kp0 + 1][sr] = h2u(xv.z, xv.w);
            Wh[nb][kp0][sr]     = h2u(wv.x, wv.y);
            Wh[nb][kp0 + 1][sr] = h2u(wv.z, wv.w);
            __syncthreads();
        }
    }

#pragma unroll
    for (int mt = 0; mt < 2; mt++) {
        int row = m0 + wm * 32 + mt * 16 + lg;
#pragma unroll
        for (int nt = 0; nt < 2; nt++) {
            int col = n0 + wn * 16 + nt * 8 + 2 * lk;
            *(float2*)(Out + row * Dx + col)       = make_float2(c[mt][nt][0], c[mt][nt][1]);
            *(float2*)(Out + (row + 8) * Dx + col) = make_float2(c[mt][nt][2], c[mt][nt][3]);
        }
    }
}

// ---------------------------------------------------------------------------
// Kernel 2: edge scores + mask + softmax -> g_W, tail casts folded in. (R8)
// ---------------------------------------------------------------------------
__global__ __launch_bounds__(256) void edge_kernel(
    const int* __restrict__ dep,
    const float* __restrict__ w2,
    const int* __restrict__ wl,
    float* __restrict__ dst)   // out + BLD, or nullptr
{
    int b  = blockIdx.y;
    int i0 = blockIdx.x * 8;

    __shared__ __align__(16) float Ash2[8][520];
    __shared__ __align__(16) float w2d[512];
    __shared__ __align__(16) float Bt[2][16][258];
    __shared__ float redmx[2][8], redsum[2][8];

    int tid = threadIdx.x;

#pragma unroll
    for (int p = 0; p < 2; p++) {
        int e = tid * 4 + p * 1024;
        int il = e >> 8, cc = e & 255;
        float4 v = *(const float4*)(g_A + (b * Lx + i0 + il) * Dx + cc);
        *(u64*)&Ash2[il][2 * cc]     = pack2(v.x, v.x);
        *(u64*)&Ash2[il][2 * cc + 2] = pack2(v.y, v.y);
        *(u64*)&Ash2[il][2 * cc + 4] = pack2(v.z, v.z);
        *(u64*)&Ash2[il][2 * cc + 6] = pack2(v.w, v.w);
    }
    {
        float v = w2[tid];
        *(u64*)&w2d[2 * tid] = pack2(v, v);
    }
    if (dst && blockIdx.x == 0 && blockIdx.y == 0 && tid < Bx)
        dst[tid] = (float)wl[tid];
    float* depout = dst ? dst + Bx : nullptr;

    const float* Bbase = g_Bm + b * Lx * Dx;

    float4 pf[4];
#pragma unroll
    for (int p = 0; p < 4; p++) {
        int e = tid * 4 + p * 1024;
        int j = e >> 4, cl = e & 15;
        pf[p] = *(const float4*)(Bbase + j * Dx + cl);
    }
#pragma unroll
    for (int p = 0; p < 4; p++) {
        int e = tid * 4 + p * 1024;
        int j = e >> 4, cl = e & 15;
        Bt[0][cl + 0][j] = pf[p].x; Bt[0][cl + 1][j] = pf[p].y;
        Bt[0][cl + 2][j] = pf[p].z; Bt[0][cl + 3][j] = pf[p].w;
    }
    __syncthreads();

    int w  = tid >> 5;
    int jl = tid & 31;
    int jh = w >> 2;
    int wr = w & 3;
    int r0 = wr * 2, r1 = r0 + 1;
    int jbase = jh * 128;

    u64 acc0[2] = {0, 0}, acc1[2] = {0, 0};

#pragma unroll 1
    for (int ch = 0; ch < 16; ch++) {
        int buf = ch & 1;
        if (ch < 15) {
            int c0 = (ch + 1) * 16;
#pragma unroll
            for (int p = 0; p < 4; p++) {
                int e = tid * 4 + p * 1024;
                int j = e >> 4, cl = e & 15;
                pf[p] = *(const float4*)(Bbase + j * Dx + c0 + cl);
            }
        }
#pragma unroll
        for (int c2 = 0; c2 < 8; c2++) {
            int cbase = ch * 16 + c2 * 2;
            ulonglong2 A0 = *(const ulonglong2*)&Ash2[r0][cbase * 2];
            ulonglong2 A1 = *(const ulonglong2*)&Ash2[r1][cbase * 2];
            ulonglong2 UU = *(const ulonglong2*)&w2d[cbase * 2];
#pragma unroll
            for (int cc = 0; cc < 2; cc++) {
                u64 a0 = cc ? A0.y : A0.x;
                u64 a1 = cc ? A1.y : A1.x;
                u64 up = cc ? UU.y : UU.x;
                int cl = c2 * 2 + cc;
#pragma unroll
                for (int gp = 0; gp < 2; gp++) {
                    u64 bt = *(const u64*)&Bt[buf][cl][jbase + gp * 64 + jl * 2];
                    acc0[gp] = ffma2(fmax2z(fadd2(a0, bt)), up, acc0[gp]);
                    acc1[gp] = ffma2(fmax2z(fadd2(a1, bt)), up, acc1[gp]);
                }
            }
        }
        if (ch < 15) {
            int nb = buf ^ 1;
#pragma unroll
            for (int p = 0; p < 4; p++) {
                int e = tid * 4 + p * 1024;
                int j = e >> 4, cl = e & 15;
                Bt[nb][cl + 0][j] = pf[p].x; Bt[nb][cl + 1][j] = pf[p].y;
                Bt[nb][cl + 2][j] = pf[p].z; Bt[nb][cl + 3][j] = pf[p].w;
            }
            __syncthreads();
        }
    }

    int gi0 = b * Lx + i0 + r0;
    int gi1 = b * Lx + i0 + r1;
    float T0[4], T1[4];
    int   mk0[4], mk1[4];
    float mx0 = -1e30f, mx1 = -1e30f;
#pragma unroll
    for (int gp = 0; gp < 2; gp++) {
        int j0 = jbase + gp * 64 + jl * 2;
        int2 m0v = *(const int2*)(dep + gi0 * Lx + j0);
        int2 m1v = *(const int2*)(dep + gi1 * Lx + j0);
        float lo, hi;
        unpack2(acc0[gp], lo, hi);
        mk0[2*gp]   = (m0v.x > 0);
        mk0[2*gp+1] = (m0v.y > 0);
        T0[2*gp]    = mk0[2*gp]   ? lo : -100.0f;
        T0[2*gp+1]  = mk0[2*gp+1] ? hi : -100.0f;
        unpack2(acc1[gp], lo, hi);
        mk1[2*gp]   = (m1v.x > 0);
        mk1[2*gp+1] = (m1v.y > 0);
        T1[2*gp]    = mk1[2*gp]   ? lo : -100.0f;
        T1[2*gp+1]  = mk1[2*gp+1] ? hi : -100.0f;
        mx0 = fmaxf(mx0, fmaxf(T0[2*gp], T0[2*gp+1]));
        mx1 = fmaxf(mx1, fmaxf(T1[2*gp], T1[2*gp+1]));
        if (depout) {
            *(float2*)(depout + gi0 * Lx + j0) = make_float2((float)m0v.x, (float)m0v.y);
            *(float2*)(depout + gi1 * Lx + j0) = make_float2((float)m1v.x, (float)m1v.y);
        }
    }
#pragma unroll
    for (int off = 16; off > 0; off >>= 1) {
        mx0 = fmaxf(mx0, __shfl_xor_sync(0xffffffffu, mx0, off));
        mx1 = fmaxf(mx1, __shfl_xor_sync(0xffffffffu, mx1, off));
    }
    if (jl == 0) { redmx[jh][r0] = mx0; redmx[jh][r1] = mx1; }
    __syncthreads();
    float gmx0 = fmaxf(redmx[0][r0], redmx[1][r0]);
    float gmx1 = fmaxf(redmx[0][r1], redmx[1][r1]);

    float E0[4], E1[4], sum0 = 0.f, sum1 = 0.f;
#pragma unroll
    for (int g = 0; g < 4; g++) {
        E0[g] = expf(T0[g] - gmx0); sum0 += E0[g];
        E1[g] = expf(T1[g] - gmx1); sum1 += E1[g];
    }
#pragma unroll
    for (int off = 16; off > 0; off >>= 1) {
        sum0 += __shfl_xor_sync(0xffffffffu, sum0, off);
        sum1 += __shfl_xor_sync(0xffffffffu, sum1, off);
    }
    if (jl == 0) { redsum[jh][r0] = sum0; redsum[jh][r1] = sum1; }
    __syncthreads();
    float inv0 = 1.0f / (redsum[0][r0] + redsum[1][r0]);
    float inv1 = 1.0f / (redsum[0][r1] + redsum[1][r1]);

#pragma unroll
    for (int gp = 0; gp < 2; gp++) {
        int j0 = jbase + gp * 64 + jl * 2;
        float2 o0, o1;
        o0.x = mk0[2*gp]   ? E0[2*gp]   * inv0 : 0.f;
        o0.y = mk0[2*gp+1] ? E0[2*gp+1] * inv0 : 0.f;
        o1.x = mk1[2*gp]   ? E1[2*gp]   * inv1 : 0.f;
        o1.y = mk1[2*gp+1] ? E1[2*gp+1] * inv1 : 0.f;
        *(float2*)(g_W + gi0 * Lx + j0) = o0;
        *(float2*)(g_W + gi1 * Lx + j0) = o1;
    }
}

// ---------------------------------------------------------------------------
// Kernel 3: agg via fp16 HMMA m16n8k16 + fused epilogue. out = relu(Q + w@H).
// Block 32i x 64c, 256 thr = 8 warps (2m16 x 4n16), warp tile 16x16.
// Wt [kp][i] stride 40; Hs [kp][c] stride 72. 8 LDS + 2 HMMA per iter/warp.
// grid (8, 4, 8) = 256 blocks.
// ---------------------------------------------------------------------------
__global__ __launch_bounds__(256) void agg_kernel(
    const float* __restrict__ Q,
    float* __restrict__ out)
{
    int b  = blockIdx.z;
    int i0 = blockIdx.x * 32;
    int c0 = blockIdx.y * 64;

    __shared__ u32 Wt[2][8][40];   // [kp][i], packed (j, j+1) fp16
    __shared__ u32 Hs[2][8][72];   // [kp][c]

    int tid = threadIdx.x;
    int wid = tid >> 5, lane = tid & 31;
    int wm = wid & 1;
    int wn = wid >> 1;
    int lg = lane >> 2, lk = lane & 3;

    // W staging: thread si = tid&31 (i-row), kpw = tid>>5 (k-pair 0..7)
    int si  = tid & 31;
    int kpw = tid >> 5;
    // H staging: warp j2 = wid (k-pair), lane covers 2 c each
    int hj2 = wid;               // 0..7
    int hc  = lane * 2;          // 0..62

    const float* Wg  = g_W + (b * Lx + i0 + si) * Lx + kpw * 2;
    const float* Hg0 = g_H + (b * Lx + 2 * hj2) * Dx + c0 + hc;
    const float* Hg1 = Hg0 + Dx;

    float2 wv = *(const float2*)Wg;
    float2 h0 = *(const float2*)Hg0;
    float2 h1 = *(const float2*)Hg1;
    Wt[0][kpw][si]    = h2u(wv.x, wv.y);
    Hs[0][hj2][hc]     = h2u(h0.x, h1.x);
    Hs[0][hj2][hc + 1] = h2u(h0.y, h1.y);
    __syncthreads();

    float c[2][4];
#pragma unroll
    for (int nt = 0; nt < 2; nt++)
#pragma unroll
        for (int q = 0; q < 4; q++) c[nt][q] = 0.f;

#pragma unroll 1
    for (int it = 0; it < 16; it++) {
        int buf = it & 1;
        if (it < 15) {
            wv = *(const float2*)(Wg + (it + 1) * 16);
            h0 = *(const float2*)(Hg0 + (it + 1) * 16 * Dx);
            h1 = *(const float2*)(Hg1 + (it + 1) * 16 * Dx);
        }
        u32 a[4], bfr[2][2];
        int mb = wm * 16;
        a[0] = Wt[buf][lk][mb + lg];
        a[1] = Wt[buf][lk][mb + lg + 8];
        a[2] = Wt[buf][lk + 4][mb + lg];
        a[3] = Wt[buf][lk + 4][mb + lg + 8];
#pragma unroll
        for (int nt = 0; nt < 2; nt++) {
            int cb = wn * 16 + nt * 8;
            bfr[nt][0] = Hs[buf][lk][cb + lg];
            bfr[nt][1] = Hs[buf][lk + 4][cb + lg];
        }
#pragma unroll
        for (int nt = 0; nt < 2; nt++)
            mma_f16(c[nt], a, bfr[nt]);

        if (it < 15) {
            int nb = buf ^ 1;
            Wt[nb][kpw][si]    = h2u(wv.x, wv.y);
            Hs[nb][hj2][hc]     = h2u(h0.x, h1.x);
            Hs[nb][hj2][hc + 1] = h2u(h0.y, h1.y);
            __syncthreads();
        }
    }

#pragma unroll
    for (int nt = 0; nt < 2; nt++) {
        int col  = c0 + wn * 16 + nt * 8 + 2 * lk;
        int row0 = i0 + wm * 16 + lg;
        long base0 = (long)(b * Lx + row0) * Dx + col;
        long base1 = (long)(b * Lx + row0 + 8) * Dx + col;
        float2 q0 = *(const float2*)(Q + base0);
        float2 q1 = *(const float2*)(Q + base1);
        *(float2*)(out + base0) = make_float2(fmaxf(q0.x + c[nt][0], 0.f),
                                              fmaxf(q0.y + c[nt][1], 0.f));
        *(float2*)(out + base1) = make_float2(fmaxf(q1.x + c[nt][2], 0.f),
                                              fmaxf(q1.y + c[nt][3], 0.f));
    }
}

// ---------------------------------------------------------------------------
extern "C" void kernel_launch(void* const* d_in, const int* in_sizes, int n_in,
                              void* d_out, int out_size)
{
    const float* Q   = (const float*)d_in[0];
    const int*   wl  = (const int*)d_in[1];
    const int*   dep = (const int*)d_in[2];
    const float* Wa  = (const float*)d_in[3];
    const float* Wb  = (const float*)d_in[4];
    const float* w2  = (const float*)d_in[5];
    const float* Wd  = (const float*)d_in[6];
    float* out = (float*)d_out;

    float* dst = (out_size >= BLD + Bx + BLL) ? out + BLD : nullptr;

    // projections via fp16 HMMA m16n8k16 (384 blocks x 256 thr)
    proj_kernel<<<dim3(32, 4, 3), 256>>>(Q, Wa, Wb, Wd);
    // edge scores + softmax -> g_W (+ tail casts) (256 blocks x 256 thr)
    edge_kernel<<<dim3(32, Bx), 256>>>(dep, w2, wl, dst);
    // aggregation via fp16 HMMA + fused residual relu (256 blocks x 256 thr)
    agg_kernel<<<dim3(8, 4, Bx), 256>>>(Q, out);
}

// round 12
// speedup vs baseline: 1.3729x; 1.0057x over previous
#include <cuda_runtime.h>
#include <cuda_fp16.h>

// Problem constants
#define Bx 8
#define Lx 256
#define Dx 256
#define BLD (Bx*Lx*Dx)   // 524288
#define BLL (Bx*Lx*Lx)   // 524288

typedef unsigned int u32;
typedef unsigned long long u64;

// Scratch (device globals — no allocation allowed)
__device__ float g_A[BLD], g_Bm[BLD], g_H[BLD];
__device__ float g_W[BLL];

// ---- fp16 m16n8k16 mma (fp32 accum) ---------------------------------------
__device__ __forceinline__ void mma_f16(float c[4], const u32 a[4], const u32 b[2]) {
    asm volatile(
        "mma.sync.aligned.m16n8k16.row.col.f32.f16.f16.f32 "
        "{%0,%1,%2,%3},{%4,%5,%6,%7},{%8,%9},{%0,%1,%2,%3};"
        : "+f"(c[0]), "+f"(c[1]), "+f"(c[2]), "+f"(c[3])
        : "r"(a[0]), "r"(a[1]), "r"(a[2]), "r"(a[3]), "r"(b[0]), "r"(b[1]));
}
__device__ __forceinline__ u32 h2u(float x, float y) {
    __half2 h = __floats2half2_rn(x, y);
    return *reinterpret_cast<u32*>(&h);
}

// ---- packed f32x2 helpers (edge kernel) ------------------------------------
__device__ __forceinline__ u64 pack2(float lo, float hi) {
    u64 r; asm("mov.b64 %0,{%1,%2};" : "=l"(r) : "f"(lo), "f"(hi)); return r;
}
__device__ __forceinline__ void unpack2(u64 v, float& lo, float& hi) {
    asm("mov.b64 {%0,%1},%2;" : "=f"(lo), "=f"(hi) : "l"(v));
}
__device__ __forceinline__ u64 ffma2(u64 a, u64 b, u64 c) {
    u64 d; asm("fma.rn.f32x2 %0,%1,%2,%3;" : "=l"(d) : "l"(a), "l"(b), "l"(c)); return d;
}
__device__ __forceinline__ u64 fadd2(u64 a, u64 b) {
    u64 d; asm("add.rn.f32x2 %0,%1,%2;" : "=l"(d) : "l"(a), "l"(b)); return d;
}
__device__ __forceinline__ u64 fmax2z(u64 a) {
    float lo, hi; unpack2(a, lo, hi);
    return pack2(fmaxf(lo, 0.f), fmaxf(hi, 0.f));
}

// ---------------------------------------------------------------------------
// Kernel 1: projections via fp16 HMMA, FULL-K smem staging (no loop barriers).
// Block 64m x 64n, 256 thr = 8 warps (2m32 x 4n16), warp tile 32x16.
// Xh/Wh: [kp][row] packed-k-pair u32, stride 72 (conflict-free fragments).
// 72 KB dynamic smem -> 3 CTA/SM. grid (32, 4, 3) = 384 blocks.
// ---------------------------------------------------------------------------
#define PROJ_SMEM (2 * 128 * 72 * 4)   // Xh[128][72] + Wh[128][72] u32

__global__ __launch_bounds__(256) void proj_kernel(
    const float* __restrict__ Q,
    const float* __restrict__ Wa,
    const float* __restrict__ Wb,
    const float* __restrict__ Wd)
{
    extern __shared__ u32 sm[];
    u32* Xh = sm;                 // [kp][row] stride 72, kp 0..127
    u32* Wh = sm + 128 * 72;

    int mat = blockIdx.z;
    const float* W = (mat == 0) ? Wa : (mat == 1) ? Wb : Wd;
    float* Out     = (mat == 0) ? g_A : (mat == 1) ? g_Bm : g_H;

    int tid  = threadIdx.x;
    int m0 = blockIdx.x * 64, n0 = blockIdx.y * 64;
    int wid = tid >> 5, lane = tid & 31;
    int wm = wid & 1;        // 2 m-halves of 32
    int wn = wid >> 1;       // 4 n-quarters of 16
    int lg = lane >> 2, lk = lane & 3;

    // ---- stage ALL of K: thread = (row sr, kp base kb), 32 kp each
    int sr = tid & 63;
    int kb = (tid >> 6) * 32;    // kp base (k base = kb*2)

    const float* xg = Q + (m0 + sr) * Dx + kb * 2;
    const float* wg = W + (n0 + sr) * Dx + kb * 2;
#pragma unroll
    for (int p = 0; p < 16; p++) {
        float4 xv = *(const float4*)(xg + p * 4);
        float4 wv = *(const float4*)(wg + p * 4);
        Xh[(kb + 2 * p) * 72 + sr]     = h2u(xv.x, xv.y);
        Xh[(kb + 2 * p + 1) * 72 + sr] = h2u(xv.z, xv.w);
        Wh[(kb + 2 * p) * 72 + sr]     = h2u(wv.x, wv.y);
        Wh[(kb + 2 * p + 1) * 72 + sr] = h2u(wv.z, wv.w);
    }
    __syncthreads();

    float c[2][2][4];
#pragma unroll
    for (int mt = 0; mt < 2; mt++)
#pragma unroll
        for (int nt = 0; nt < 2; nt++)
#pragma unroll
            for (int q = 0; q < 4; q++) c[mt][nt][q] = 0.f;

    // ---- 16 K-chunks, zero barriers, fully unrolled
#pragma unroll
    for (int ck = 0; ck < 16; ck++) {
        int kc = ck * 8;
        u32 a[2][4], bfr[2][2];
#pragma unroll
        for (int mt = 0; mt < 2; mt++) {
            int mb = wm * 32 + mt * 16;
            a[mt][0] = Xh[(kc + lk) * 72 + mb + lg];
            a[mt][1] = Xh[(kc + lk) * 72 + mb + lg + 8];
            a[mt][2] = Xh[(kc + lk + 4) * 72 + mb + lg];
            a[mt][3] = Xh[(kc + lk + 4) * 72 + mb + lg + 8];
        }
#pragma unroll
        for (int nt = 0; nt < 2; nt++) {
            int nb = wn * 16 + nt * 8;
            bfr[nt][0] = Wh[(kc + lk) * 72 + nb + lg];
            bfr[nt][1] = Wh[(kc + lk + 4) * 72 + nb + lg];
        }
#pragma unroll
        for (int mt = 0; mt < 2; mt++)
#pragma unroll
            for (int nt = 0; nt < 2; nt++)
                mma_f16(c[mt][nt], a[mt], bfr[nt]);
    }

#pragma unroll
    for (int mt = 0; mt < 2; mt++) {
        int row = m0 + wm * 32 + mt * 16 + lg;
#pragma unroll
        for (int nt = 0; nt < 2; nt++) {
            int col = n0 + wn * 16 + nt * 8 + 2 * lk;
            *(float2*)(Out + row * Dx + col)       = make_float2(c[mt][nt][0], c[mt][nt][1]);
            *(float2*)(Out + (row + 8) * Dx + col) = make_float2(c[mt][nt][2], c[mt][nt][3]);
        }
    }
}

// ---------------------------------------------------------------------------
// Kernel 2: edge scores + mask + softmax -> g_W, tail casts folded in. (R8/R11)
// ---------------------------------------------------------------------------
__global__ __launch_bounds__(256) void edge_kernel(
    const int* __restrict__ dep,
    const float* __restrict__ w2,
    const int* __restrict__ wl,
    float* __restrict__ dst)   // out + BLD, or nullptr
{
    int b  = blockIdx.y;
    int i0 = blockIdx.x * 8;

    __shared__ __align__(16) float Ash2[8][520];
    __shared__ __align__(16) float w2d[512];
    __shared__ __align__(16) float Bt[2][16][258];
    __shared__ float redmx[2][8], redsum[2][8];

    int tid = threadIdx.x;

#pragma unroll
    for (int p = 0; p < 2; p++) {
        int e = tid * 4 + p * 1024;
        int il = e >> 8, cc = e & 255;
        float4 v = *(const float4*)(g_A + (b * Lx + i0 + il) * Dx + cc);
        *(u64*)&Ash2[il][2 * cc]     = pack2(v.x, v.x);
        *(u64*)&Ash2[il][2 * cc + 2] = pack2(v.y, v.y);
        *(u64*)&Ash2[il][2 * cc + 4] = pack2(v.z, v.z);
        *(u64*)&Ash2[il][2 * cc + 6] = pack2(v.w, v.w);
    }
    {
        float v = w2[tid];
        *(u64*)&w2d[2 * tid] = pack2(v, v);
    }
    if (dst && blockIdx.x == 0 && blockIdx.y == 0 && tid < Bx)
        dst[tid] = (float)wl[tid];
    float* depout = dst ? dst + Bx : nullptr;

    const float* Bbase = g_Bm + b * Lx * Dx;

    float4 pf[4];
#pragma unroll
    for (int p = 0; p < 4; p++) {
        int e = tid * 4 + p * 1024;
        int j = e >> 4, cl = e & 15;
        pf[p] = *(const float4*)(Bbase + j * Dx + cl);
    }
#pragma unroll
    for (int p = 0; p < 4; p++) {
        int e = tid * 4 + p * 1024;
        int j = e >> 4, cl = e & 15;
        Bt[0][cl + 0][j] = pf[p].x; Bt[0][cl + 1][j] = pf[p].y;
        Bt[0][cl + 2][j] = pf[p].z; Bt[0][cl + 3][j] = pf[p].w;
    }
    __syncthreads();

    int w  = tid >> 5;
    int jl = tid & 31;
    int jh = w >> 2;
    int wr = w & 3;
    int r0 = wr * 2, r1 = r0 + 1;
    int jbase = jh * 128;

    u64 acc0[2] = {0, 0}, acc1[2] = {0, 0};

#pragma unroll 1
    for (int ch = 0; ch < 16; ch++) {
        int buf = ch & 1;
        if (ch < 15) {
            int c0 = (ch + 1) * 16;
#pragma unroll
            for (int p = 0; p < 4; p++) {
                int e = tid * 4 + p * 1024;
                int j = e >> 4, cl = e & 15;
                pf[p] = *(const float4*)(Bbase + j * Dx + c0 + cl);
            }
        }
#pragma unroll
        for (int c2 = 0; c2 < 8; c2++) {
            int cbase = ch * 16 + c2 * 2;
            ulonglong2 A0 = *(const ulonglong2*)&Ash2[r0][cbase * 2];
            ulonglong2 A1 = *(const ulonglong2*)&Ash2[r1][cbase * 2];
            ulonglong2 UU = *(const ulonglong2*)&w2d[cbase * 2];
#pragma unroll
            for (int cc = 0; cc < 2; cc++) {
                u64 a0 = cc ? A0.y : A0.x;
                u64 a1 = cc ? A1.y : A1.x;
                u64 up = cc ? UU.y : UU.x;
                int cl = c2 * 2 + cc;
#pragma unroll
                for (int gp = 0; gp < 2; gp++) {
                    u64 bt = *(const u64*)&Bt[buf][cl][jbase + gp * 64 + jl * 2];
                    acc0[gp] = ffma2(fmax2z(fadd2(a0, bt)), up, acc0[gp]);
                    acc1[gp] = ffma2(fmax2z(fadd2(a1, bt)), up, acc1[gp]);
                }
            }
        }
        if (ch < 15) {
            int nb = buf ^ 1;
#pragma unroll
            for (int p = 0; p < 4; p++) {
                int e = tid * 4 + p * 1024;
                int j = e >> 4, cl = e & 15;
                Bt[nb][cl + 0][j] = pf[p].x; Bt[nb][cl + 1][j] = pf[p].y;
                Bt[nb][cl + 2][j] = pf[p].z; Bt[nb][cl + 3][j] = pf[p].w;
            }
            __syncthreads();
        }
    }

    int gi0 = b * Lx + i0 + r0;
    int gi1 = b * Lx + i0 + r1;
    float T0[4], T1[4];
    int   mk0[4], mk1[4];
    float mx0 = -1e30f, mx1 = -1e30f;
#pragma unroll
    for (int gp = 0; gp < 2; gp++) {
        int j0 = jbase + gp * 64 + jl * 2;
        int2 m0v = *(const int2*)(dep + gi0 * Lx + j0);
        int2 m1v = *(const int2*)(dep + gi1 * Lx + j0);
        float lo, hi;
        unpack2(acc0[gp], lo, hi);
        mk0[2*gp]   = (m0v.x > 0);
        mk0[2*gp+1] = (m0v.y > 0);
        T0[2*gp]    = mk0[2*gp]   ? lo : -100.0f;
        T0[2*gp+1]  = mk0[2*gp+1] ? hi : -100.0f;
        unpack2(acc1[gp], lo, hi);
        mk1[2*gp]   = (m1v.x > 0);
        mk1[2*gp+1] = (m1v.y > 0);
        T1[2*gp]    = mk1[2*gp]   ? lo : -100.0f;
        T1[2*gp+1]  = mk1[2*gp+1] ? hi : -100.0f;
        mx0 = fmaxf(mx0, fmaxf(T0[2*gp], T0[2*gp+1]));
        mx1 = fmaxf(mx1, fmaxf(T1[2*gp], T1[2*gp+1]));
        if (depout) {
            *(float2*)(depout + gi0 * Lx + j0) = make_float2((float)m0v.x, (float)m0v.y);
            *(float2*)(depout + gi1 * Lx + j0) = make_float2((float)m1v.x, (float)m1v.y);
        }
    }
#pragma unroll
    for (int off = 16; off > 0; off >>= 1) {
        mx0 = fmaxf(mx0, __shfl_xor_sync(0xffffffffu, mx0, off));
        mx1 = fmaxf(mx1, __shfl_xor_sync(0xffffffffu, mx1, off));
    }
    if (jl == 0) { redmx[jh][r0] = mx0; redmx[jh][r1] = mx1; }
    __syncthreads();
    float gmx0 = fmaxf(redmx[0][r0], redmx[1][r0]);
    float gmx1 = fmaxf(redmx[0][r1], redmx[1][r1]);

    float E0[4], E1[4], sum0 = 0.f, sum1 = 0.f;
#pragma unroll
    for (int g = 0; g < 4; g++) {
        E0[g] = expf(T0[g] - gmx0); sum0 += E0[g];
        E1[g] = expf(T1[g] - gmx1); sum1 += E1[g];
    }
#pragma unroll
    for (int off = 16; off > 0; off >>= 1) {
        sum0 += __shfl_xor_sync(0xffffffffu, sum0, off);
        sum1 += __shfl_xor_sync(0xffffffffu, sum1, off);
    }
    if (jl == 0) { redsum[jh][r0] = sum0; redsum[jh][r1] = sum1; }
    __syncthreads();
    float inv0 = 1.0f / (redsum[0][r0] + redsum[1][r0]);
    float inv1 = 1.0f / (redsum[0][r1] + redsum[1][r1]);

#pragma unroll
    for (int gp = 0; gp < 2; gp++) {
        int j0 = jbase + gp * 64 + jl * 2;
        float2 o0, o1;
        o0.x = mk0[2*gp]   ? E0[2*gp]   * inv0 : 0.f;
        o0.y = mk0[2*gp+1] ? E0[2*gp+1] * inv0 : 0.f;
        o1.x = mk1[2*gp]   ? E1[2*gp]   * inv1 : 0.f;
        o1.y = mk1[2*gp+1] ? E1[2*gp+1] * inv1 : 0.f;
        *(float2*)(g_W + gi0 * Lx + j0) = o0;
        *(float2*)(g_W + gi1 * Lx + j0) = o1;
    }
}

// ---------------------------------------------------------------------------
// Kernel 3: agg via fp16 HMMA, FULL-K smem staging (no loop barriers).
// out = relu(Q + w@H). Block 32i x 64c, 256 thr = 8 warps (2m16 x 4n16).
// Wt [kp][i] stride 40; Hs [kp][c] stride 72. 56 KB smem -> 4 CTA/SM.
// grid (8, 4, 8) = 256 blocks.
// ---------------------------------------------------------------------------
#define AGG_SMEM ((128 * 40 + 128 * 72) * 4)

__global__ __launch_bounds__(256) void agg_kernel(
    const float* __restrict__ Q,
    float* __restrict__ out)
{
    extern __shared__ u32 sm[];
    u32* Wt = sm;                 // [kp][i] stride 40
    u32* Hs = sm + 128 * 40;      // [kp][c] stride 72

    int b  = blockIdx.z;
    int i0 = blockIdx.x * 32;
    int c0 = blockIdx.y * 64;

    int tid = threadIdx.x;
    int wid = tid >> 5, lane = tid & 31;
    int wm = wid & 1;
    int wn = wid >> 1;
    int lg = lane >> 2, lk = lane & 3;

    // ---- stage all W: thread = (i-row si, kp base kb), 16 kp each
    {
        int si = tid & 31;
        int kb = (tid >> 5) * 16;
        const float* Wg = g_W + (b * Lx + i0 + si) * Lx + kb * 2;
#pragma unroll
        for (int p = 0; p < 8; p++) {
            float4 v = *(const float4*)(Wg + p * 4);
            Wt[(kb + 2 * p) * 40 + si]     = h2u(v.x, v.y);
            Wt[(kb + 2 * p + 1) * 40 + si] = h2u(v.z, v.w);
        }
    }
    // ---- stage all H: slot = (kp, c-pair)
#pragma unroll
    for (int p = 0; p < 16; p++) {
        int idx = p * 256 + tid;
        int kp = idx >> 5, c2 = (idx & 31) * 2;
        const float* Hg = g_H + (b * Lx + 2 * kp) * Dx + c0 + c2;
        float2 h0 = *(const float2*)Hg;
        float2 h1 = *(const float2*)(Hg + Dx);
        Hs[kp * 72 + c2]     = h2u(h0.x, h1.x);
        Hs[kp * 72 + c2 + 1] = h2u(h0.y, h1.y);
    }
    __syncthreads();

    float c[2][4];
#pragma unroll
    for (int nt = 0; nt < 2; nt++)
#pragma unroll
        for (int q = 0; q < 4; q++) c[nt][q] = 0.f;

#pragma unroll
    for (int ck = 0; ck < 16; ck++) {
        int kc = ck * 8;
        u32 a[4], bfr[2][2];
        int mb = wm * 16;
        a[0] = Wt[(kc + lk) * 40 + mb + lg];
        a[1] = Wt[(kc + lk) * 40 + mb + lg + 8];
        a[2] = Wt[(kc + lk + 4) * 40 + mb + lg];
        a[3] = Wt[(kc + lk + 4) * 40 + mb + lg + 8];
#pragma unroll
        for (int nt = 0; nt < 2; nt++) {
            int cb = wn * 16 + nt * 8;
            bfr[nt][0] = Hs[(kc + lk) * 72 + cb + lg];
            bfr[nt][1] = Hs[(kc + lk + 4) * 72 + cb + lg];
        }
#pragma unroll
        for (int nt = 0; nt < 2; nt++)
            mma_f16(c[nt], a, bfr[nt]);
    }

#pragma unroll
    for (int nt = 0; nt < 2; nt++) {
        int col  = c0 + wn * 16 + nt * 8 + 2 * lk;
        int row0 = i0 + wm * 16 + lg;
        long base0 = (long)(b * Lx + row0) * Dx + col;
        long base1 = (long)(b * Lx + row0 + 8) * Dx + col;
        float2 q0 = *(const float2*)(Q + base0);
        float2 q1 = *(const float2*)(Q + base1);
        *(float2*)(out + base0) = make_float2(fmaxf(q0.x + c[nt][0], 0.f),
                                              fmaxf(q0.y + c[nt][1], 0.f));
        *(float2*)(out + base1) = make_float2(fmaxf(q1.x + c[nt][2], 0.f),
                                              fmaxf(q1.y + c[nt][3], 0.f));
    }
}

// ---------------------------------------------------------------------------
extern "C" void kernel_launch(void* const* d_in, const int* in_sizes, int n_in,
                              void* d_out, int out_size)
{
    const float* Q   = (const float*)d_in[0];
    const int*   wl  = (const int*)d_in[1];
    const int*   dep = (const int*)d_in[2];
    const float* Wa  = (const float*)d_in[3];
    const float* Wb  = (const float*)d_in[4];
    const float* w2  = (const float*)d_in[5];
    const float* Wd  = (const float*)d_in[6];
    float* out = (float*)d_out;

    float* dst = (out_size >= BLD + Bx + BLL) ? out + BLD : nullptr;

    static bool attr_set = false;
    if (!attr_set) {
        cudaFuncSetAttribute(proj_kernel, cudaFuncAttributeMaxDynamicSharedMemorySize, PROJ_SMEM);
        cudaFuncSetAttribute(agg_kernel,  cudaFuncAttributeMaxDynamicSharedMemorySize, AGG_SMEM);
        attr_set = true;
    }

    // projections via fp16 HMMA, full-K staging (384 blocks x 256 thr)
    proj_kernel<<<dim3(32, 4, 3), 256, PROJ_SMEM>>>(Q, Wa, Wb, Wd);
    // edge scores + softmax -> g_W (+ tail casts) (256 blocks x 256 thr)
    edge_kernel<<<dim3(32, Bx), 256>>>(dep, w2, wl, dst);
    // aggregation via fp16 HMMA, full-K staging + fused residual relu
    agg_kernel<<<dim3(8, 4, Bx), 256, AGG_SMEM>>>(Q, out);
}

// round 13
// speedup vs baseline: 1.8750x; 1.3658x over previous
#include <cuda_runtime.h>
#include <cuda_fp16.h>

// Problem constants
#define Bx 8
#define Lx 256
#define Dx 256
#define BLD (Bx*Lx*Dx)   // 524288
#define BLL (Bx*Lx*Lx)   // 524288

typedef unsigned int u32;
typedef unsigned long long u64;

// Scratch (device globals — no allocation allowed)
__device__ float g_A[BLD], g_Bm[BLD], g_H[BLD];
__device__ float g_W[BLL];

// ---- fp16 m16n8k16 mma (fp32 accum) ---------------------------------------
__device__ __forceinline__ void mma_f16(float c[4], const u32 a[4], const u32 b[2]) {
    asm volatile(
        "mma.sync.aligned.m16n8k16.row.col.f32.f16.f16.f32 "
        "{%0,%1,%2,%3},{%4,%5,%6,%7},{%8,%9},{%0,%1,%2,%3};"
        : "+f"(c[0]), "+f"(c[1]), "+f"(c[2]), "+f"(c[3])
        : "r"(a[0]), "r"(a[1]), "r"(a[2]), "r"(a[3]), "r"(b[0]), "r"(b[1]));
}
__device__ __forceinline__ u32 h2u(float x, float y) {
    __half2 h = __floats2half2_rn(x, y);
    return *reinterpret_cast<u32*>(&h);
}
__device__ __forceinline__ u64 packh4(float4 v) {   // (k,k+1)|(k+2,k+3) fp16x4
    return ((u64)h2u(v.z, v.w) << 32) | (u64)h2u(v.x, v.y);
}

// ---- packed f32x2 helpers (edge kernel) ------------------------------------
__device__ __forceinline__ u64 pack2(float lo, float hi) {
    u64 r; asm("mov.b64 %0,{%1,%2};" : "=l"(r) : "f"(lo), "f"(hi)); return r;
}
__device__ __forceinline__ void unpack2(u64 v, float& lo, float& hi) {
    asm("mov.b64 {%0,%1},%2;" : "=f"(lo), "=f"(hi) : "l"(v));
}
__device__ __forceinline__ u64 ffma2(u64 a, u64 b, u64 c) {
    u64 d; asm("fma.rn.f32x2 %0,%1,%2,%3;" : "=l"(d) : "l"(a), "l"(b), "l"(c)); return d;
}
__device__ __forceinline__ u64 fadd2(u64 a, u64 b) {
    u64 d; asm("add.rn.f32x2 %0,%1,%2;" : "=l"(d) : "l"(a), "l"(b)); return d;
}
__device__ __forceinline__ u64 fmax2z(u64 a) {
    float lo, hi; unpack2(a, lo, hi);
    return pack2(fmaxf(lo, 0.f), fmaxf(hi, 0.f));
}

// ---------------------------------------------------------------------------
// Kernel 1: projections via fp16 HMMA, full-K staging, COALESCED loads.
// Block 64m x 64n, 256 thr = 8 warps (2m32 x 4n16), warp tile 32x16.
// Smem layout [row][kp], stride 132 (132 = 4 mod 32 -> fragment banks
// 4*lg+lk cover 0..31: conflict-free). Staging: lanes sweep consecutive
// 16B chunks (fully coalesced LDG.128), u64 smem stores.
// 68 KB dynamic smem -> 3 CTA/SM. grid (32, 4, 3) = 384 blocks.
// ---------------------------------------------------------------------------
#define XW_STRIDE 132
#define PROJ_SMEM (2 * 64 * XW_STRIDE * 4)

__global__ __launch_bounds__(256) void proj_kernel(
    const float* __restrict__ Q,
    const float* __restrict__ Wa,
    const float* __restrict__ Wb,
    const float* __restrict__ Wd)
{
    extern __shared__ u32 sm[];
    u32* Xh = sm;                        // [row][kp], stride 132
    u32* Wh = sm + 64 * XW_STRIDE;

    int mat = blockIdx.z;
    const float* W = (mat == 0) ? Wa : (mat == 1) ? Wb : Wd;
    float* Out     = (mat == 0) ? g_A : (mat == 1) ? g_Bm : g_H;

    int tid  = threadIdx.x;
    int m0 = blockIdx.x * 64, n0 = blockIdx.y * 64;
    int wid = tid >> 5, lane = tid & 31;
    int wm = wid & 1;        // 2 m-halves of 32
    int wn = wid >> 1;       // 4 n-quarters of 16
    int lg = lane >> 2, lk = lane & 3;

    // ---- stage ALL of K, coalesced: chunk = (row, c4), lanes sweep c4
#pragma unroll
    for (int p = 0; p < 16; p++) {
        int idx = p * 256 + tid;
        int row = idx >> 6, c4 = idx & 63;
        float4 xv = *(const float4*)(Q + (m0 + row) * Dx + c4 * 4);
        float4 wv = *(const float4*)(W + (n0 + row) * Dx + c4 * 4);
        *(u64*)&Xh[row * XW_STRIDE + c4 * 2] = packh4(xv);
        *(u64*)&Wh[row * XW_STRIDE + c4 * 2] = packh4(wv);
    }
    __syncthreads();

    float c[2][2][4];
#pragma unroll
    for (int mt = 0; mt < 2; mt++)
#pragma unroll
        for (int nt = 0; nt < 2; nt++)
#pragma unroll
            for (int q = 0; q < 4; q++) c[mt][nt][q] = 0.f;

    // ---- 16 K-chunks, no barriers, fully unrolled
#pragma unroll
    for (int ck = 0; ck < 16; ck++) {
        int kc = ck * 8;
        u32 a[2][4], bfr[2][2];
#pragma unroll
        for (int mt = 0; mt < 2; mt++) {
            int mb = wm * 32 + mt * 16;
            a[mt][0] = Xh[(mb + lg) * XW_STRIDE + kc + lk];
            a[mt][1] = Xh[(mb + lg + 8) * XW_STRIDE + kc + lk];
            a[mt][2] = Xh[(mb + lg) * XW_STRIDE + kc + lk + 4];
            a[mt][3] = Xh[(mb + lg + 8) * XW_STRIDE + kc + lk + 4];
        }
#pragma unroll
        for (int nt = 0; nt < 2; nt++) {
            int nb = wn * 16 + nt * 8;
            bfr[nt][0] = Wh[(nb + lg) * XW_STRIDE + kc + lk];
            bfr[nt][1] = Wh[(nb + lg) * XW_STRIDE + kc + lk + 4];
        }
#pragma unroll
        for (int mt = 0; mt < 2; mt++)
#pragma unroll
            for (int nt = 0; nt < 2; nt++)
                mma_f16(c[mt][nt], a[mt], bfr[nt]);
    }

#pragma unroll
    for (int mt = 0; mt < 2; mt++) {
        int row = m0 + wm * 32 + mt * 16 + lg;
#pragma unroll
        for (int nt = 0; nt < 2; nt++) {
            int col = n0 + wn * 16 + nt * 8 + 2 * lk;
            *(float2*)(Out + row * Dx + col)       = make_float2(c[mt][nt][0], c[mt][nt][1]);
            *(float2*)(Out + (row + 8) * Dx + col) = make_float2(c[mt][nt][2], c[mt][nt][3]);
        }
    }
}

// ---------------------------------------------------------------------------
// Kernel 2: edge scores + mask + softmax -> g_W, tail casts folded in. (R8)
// ---------------------------------------------------------------------------
__global__ __launch_bounds__(256) void edge_kernel(
    const int* __restrict__ dep,
    const float* __restrict__ w2,
    const int* __restrict__ wl,
    float* __restrict__ dst)   // out + BLD, or nullptr
{
    int b  = blockIdx.y;
    int i0 = blockIdx.x * 8;

    __shared__ __align__(16) float Ash2[8][520];
    __shared__ __align__(16) float w2d[512];
    __shared__ __align__(16) float Bt[2][16][258];
    __shared__ float redmx[2][8], redsum[2][8];

    int tid = threadIdx.x;

#pragma unroll
    for (int p = 0; p < 2; p++) {
        int e = tid * 4 + p * 1024;
        int il = e >> 8, cc = e & 255;
        float4 v = *(const float4*)(g_A + (b * Lx + i0 + il) * Dx + cc);
        *(u64*)&Ash2[il][2 * cc]     = pack2(v.x, v.x);
        *(u64*)&Ash2[il][2 * cc + 2] = pack2(v.y, v.y);
        *(u64*)&Ash2[il][2 * cc + 4] = pack2(v.z, v.z);
        *(u64*)&Ash2[il][2 * cc + 6] = pack2(v.w, v.w);
    }
    {
        float v = w2[tid];
        *(u64*)&w2d[2 * tid] = pack2(v, v);
    }
    if (dst && blockIdx.x == 0 && blockIdx.y == 0 && tid < Bx)
        dst[tid] = (float)wl[tid];
    float* depout = dst ? dst + Bx : nullptr;

    const float* Bbase = g_Bm + b * Lx * Dx;

    float4 pf[4];
#pragma unroll
    for (int p = 0; p < 4; p++) {
        int e = tid * 4 + p * 1024;
        int j = e >> 4, cl = e & 15;
        pf[p] = *(const float4*)(Bbase + j * Dx + cl);
    }
#pragma unroll
    for (int p = 0; p < 4; p++) {
        int e = tid * 4 + p * 1024;
        int j = e >> 4, cl = e & 15;
        Bt[0][cl + 0][j] = pf[p].x; Bt[0][cl + 1][j] = pf[p].y;
        Bt[0][cl + 2][j] = pf[p].z; Bt[0][cl + 3][j] = pf[p].w;
    }
    __syncthreads();

    int w  = tid >> 5;
    int jl = tid & 31;
    int jh = w >> 2;
    int wr = w & 3;
    int r0 = wr * 2, r1 = r0 + 1;
    int jbase = jh * 128;

    u64 acc0[2] = {0, 0}, acc1[2] = {0, 0};

#pragma unroll 1
    for (int ch = 0; ch < 16; ch++) {
        int buf = ch & 1;
        if (ch < 15) {
            int c0 = (ch + 1) * 16;
#pragma unroll
            for (int p = 0; p < 4; p++) {
                int e = tid * 4 + p * 1024;
                int j = e >> 4, cl = e & 15;
                pf[p] = *(const float4*)(Bbase + j * Dx + c0 + cl);
            }
        }
#pragma unroll
        for (int c2 = 0; c2 < 8; c2++) {
            int cbase = ch * 16 + c2 * 2;
            ulonglong2 A0 = *(const ulonglong2*)&Ash2[r0][cbase * 2];
            ulonglong2 A1 = *(const ulonglong2*)&Ash2[r1][cbase * 2];
            ulonglong2 UU = *(const ulonglong2*)&w2d[cbase * 2];
#pragma unroll
            for (int cc = 0; cc < 2; cc++) {
                u64 a0 = cc ? A0.y : A0.x;
                u64 a1 = cc ? A1.y : A1.x;
                u64 up = cc ? UU.y : UU.x;
                int cl = c2 * 2 + cc;
#pragma unroll
                for (int gp = 0; gp < 2; gp++) {
                    u64 bt = *(const u64*)&Bt[buf][cl][jbase + gp * 64 + jl * 2];
                    acc0[gp] = ffma2(fmax2z(fadd2(a0, bt)), up, acc0[gp]);
                    acc1[gp] = ffma2(fmax2z(fadd2(a1, bt)), up, acc1[gp]);
                }
            }
        }
        if (ch < 15) {
            int nb = buf ^ 1;
#pragma unroll
            for (int p = 0; p < 4; p++) {
                int e = tid * 4 + p * 1024;
                int j = e >> 4, cl = e & 15;
                Bt[nb][cl + 0][j] = pf[p].x; Bt[nb][cl + 1][j] = pf[p].y;
                Bt[nb][cl + 2][j] = pf[p].z; Bt[nb][cl + 3][j] = pf[p].w;
            }
            __syncthreads();
        }
    }

    int gi0 = b * Lx + i0 + r0;
    int gi1 = b * Lx + i0 + r1;
    float T0[4], T1[4];
    int   mk0[4], mk1[4];
    float mx0 = -1e30f, mx1 = -1e30f;
#pragma unroll
    for (int gp = 0; gp < 2; gp++) {
        int j0 = jbase + gp * 64 + jl * 2;
        int2 m0v = *(const int2*)(dep + gi0 * Lx + j0);
        int2 m1v = *(const int2*)(dep + gi1 * Lx + j0);
        float lo, hi;
        unpack2(acc0[gp], lo, hi);
        mk0[2*gp]   = (m0v.x > 0);
        mk0[2*gp+1] = (m0v.y > 0);
        T0[2*gp]    = mk0[2*gp]   ? lo : -100.0f;
        T0[2*gp+1]  = mk0[2*gp+1] ? hi : -100.0f;
        unpack2(acc1[gp], lo, hi);
        mk1[2*gp]   = (m1v.x > 0);
        mk1[2*gp+1] = (m1v.y > 0);
        T1[2*gp]    = mk1[2*gp]   ? lo : -100.0f;
        T1[2*gp+1]  = mk1[2*gp+1] ? hi : -100.0f;
        mx0 = fmaxf(mx0, fmaxf(T0[2*gp], T0[2*gp+1]));
        mx1 = fmaxf(mx1, fmaxf(T1[2*gp], T1[2*gp+1]));
        if (depout) {
            *(float2*)(depout + gi0 * Lx + j0) = make_float2((float)m0v.x, (float)m0v.y);
            *(float2*)(depout + gi1 * Lx + j0) = make_float2((float)m1v.x, (float)m1v.y);
        }
    }
#pragma unroll
    for (int off = 16; off > 0; off >>= 1) {
        mx0 = fmaxf(mx0, __shfl_xor_sync(0xffffffffu, mx0, off));
        mx1 = fmaxf(mx1, __shfl_xor_sync(0xffffffffu, mx1, off));
    }
    if (jl == 0) { redmx[jh][r0] = mx0; redmx[jh][r1] = mx1; }
    __syncthreads();
    float gmx0 = fmaxf(redmx[0][r0], redmx[1][r0]);
    float gmx1 = fmaxf(redmx[0][r1], redmx[1][r1]);

    float E0[4], E1[4], sum0 = 0.f, sum1 = 0.f;
#pragma unroll
    for (int g = 0; g < 4; g++) {
        E0[g] = expf(T0[g] - gmx0); sum0 += E0[g];
        E1[g] = expf(T1[g] - gmx1); sum1 += E1[g];
    }
#pragma unroll
    for (int off = 16; off > 0; off >>= 1) {
        sum0 += __shfl_xor_sync(0xffffffffu, sum0, off);
        sum1 += __shfl_xor_sync(0xffffffffu, sum1, off);
    }
    if (jl == 0) { redsum[jh][r0] = sum0; redsum[jh][r1] = sum1; }
    __syncthreads();
    float inv0 = 1.0f / (redsum[0][r0] + redsum[1][r0]);
    float inv1 = 1.0f / (redsum[0][r1] + redsum[1][r1]);

#pragma unroll
    for (int gp = 0; gp < 2; gp++) {
        int j0 = jbase + gp * 64 + jl * 2;
        float2 o0, o1;
        o0.x = mk0[2*gp]   ? E0[2*gp]   * inv0 : 0.f;
        o0.y = mk0[2*gp+1] ? E0[2*gp+1] * inv0 : 0.f;
        o1.x = mk1[2*gp]   ? E1[2*gp]   * inv1 : 0.f;
        o1.y = mk1[2*gp+1] ? E1[2*gp+1] * inv1 : 0.f;
        *(float2*)(g_W + gi0 * Lx + j0) = o0;
        *(float2*)(g_W + gi1 * Lx + j0) = o1;
    }
}

// ---------------------------------------------------------------------------
// Kernel 3: agg via fp16 HMMA, full-K staging, coalesced. out = relu(Q+w@H).
// Block 32i x 64c, 256 thr = 8 warps (2m16 x 4n16), warp tile 16x16.
// Wt [i][kp] stride 132 (conflict-free fragments, coalesced staging);
// Hs [kp][c] stride 72 (already coalesced + conflict-free).
// grid (8, 4, 8) = 256 blocks, ~54 KB smem -> 4 CTA/SM.
// ---------------------------------------------------------------------------
#define AGG_SMEM ((32 * XW_STRIDE + 128 * 72) * 4)

__global__ __launch_bounds__(256) void agg_kernel(
    const float* __restrict__ Q,
    float* __restrict__ out)
{
    extern __shared__ u32 sm[];
    u32* Wt = sm;                       // [i][kp], stride 132
    u32* Hs = sm + 32 * XW_STRIDE;      // [kp][c], stride 72

    int b  = blockIdx.z;
    int i0 = blockIdx.x * 32;
    int c0 = blockIdx.y * 64;

    int tid = threadIdx.x;
    int wid = tid >> 5, lane = tid & 31;
    int wm = wid & 1;
    int wn = wid >> 1;
    int lg = lane >> 2, lk = lane & 3;

    // ---- stage all W, coalesced: chunk = (row, c4), lanes sweep c4
#pragma unroll
    for (int p = 0; p < 8; p++) {
        int idx = p * 256 + tid;
        int row = idx >> 6, c4 = idx & 63;
        float4 v = *(const float4*)(g_W + (b * Lx + i0 + row) * Lx + c4 * 4);
        *(u64*)&Wt[row * XW_STRIDE + c4 * 2] = packh4(v);
    }
    // ---- stage all H (already coalesced): slot = (kp, c-pair)
#pragma unroll
    for (int p = 0; p < 16; p++) {
        int idx = p * 256 + tid;
        int kp = idx >> 5, c2 = (idx & 31) * 2;
        const float* Hg = g_H + (b * Lx + 2 * kp) * Dx + c0 + c2;
        float2 h0 = *(const float2*)Hg;
        float2 h1 = *(const float2*)(Hg + Dx);
        Hs[kp * 72 + c2]     = h2u(h0.x, h1.x);
        Hs[kp * 72 + c2 + 1] = h2u(h0.y, h1.y);
    }
    __syncthreads();

    float c[2][4];
#pragma unroll
    for (int nt = 0; nt < 2; nt++)
#pragma unroll
        for (int q = 0; q < 4; q++) c[nt][q] = 0.f;

#pragma unroll
    for (int ck = 0; ck < 16; ck++) {
        int kc = ck * 8;
        u32 a[4], bfr[2][2];
        int mb = wm * 16;
        a[0] = Wt[(mb + lg) * XW_STRIDE + kc + lk];
        a[1] = Wt[(mb + lg + 8) * XW_STRIDE + kc + lk];
        a[2] = Wt[(mb + lg) * XW_STRIDE + kc + lk + 4];
        a[3] = Wt[(mb + lg + 8) * XW_STRIDE + kc + lk + 4];
#pragma unroll
        for (int nt = 0; nt < 2; nt++) {
            int cb = wn * 16 + nt * 8;
            bfr[nt][0] = Hs[(kc + lk) * 72 + cb + lg];
            bfr[nt][1] = Hs[(kc + lk + 4) * 72 + cb + lg];
        }
#pragma unroll
        for (int nt = 0; nt < 2; nt++)
            mma_f16(c[nt], a, bfr[nt]);
    }

#pragma unroll
    for (int nt = 0; nt < 2; nt++) {
        int col  = c0 + wn * 16 + nt * 8 + 2 * lk;
        int row0 = i0 + wm * 16 + lg;
        long base0 = (long)(b * Lx + row0) * Dx + col;
        long base1 = (long)(b * Lx + row0 + 8) * Dx + col;
        float2 q0 = *(const float2*)(Q + base0);
        float2 q1 = *(const float2*)(Q + base1);
        *(float2*)(out + base0) = make_float2(fmaxf(q0.x + c[nt][0], 0.f),
                                              fmaxf(q0.y + c[nt][1], 0.f));
        *(float2*)(out + base1) = make_float2(fmaxf(q1.x + c[nt][2], 0.f),
                                              fmaxf(q1.y + c[nt][3], 0.f));
    }
}

// ---------------------------------------------------------------------------
extern "C" void kernel_launch(void* const* d_in, const int* in_sizes, int n_in,
                              void* d_out, int out_size)
{
    const float* Q   = (const float*)d_in[0];
    const int*   wl  = (const int*)d_in[1];
    const int*   dep = (const int*)d_in[2];
    const float* Wa  = (const float*)d_in[3];
    const float* Wb  = (const float*)d_in[4];
    const float* w2  = (const float*)d_in[5];
    const float* Wd  = (const float*)d_in[6];
    float* out = (float*)d_out;

    float* dst = (out_size >= BLD + Bx + BLL) ? out + BLD : nullptr;

    static bool attr_set = false;
    if (!attr_set) {
        cudaFuncSetAttribute(proj_kernel, cudaFuncAttributeMaxDynamicSharedMemorySize, PROJ_SMEM);
        cudaFuncSetAttribute(agg_kernel,  cudaFuncAttributeMaxDynamicSharedMemorySize, AGG_SMEM);
        attr_set = true;
    }

    // projections via fp16 HMMA, coalesced full-K staging (384 blocks)
    proj_kernel<<<dim3(32, 4, 3), 256, PROJ_SMEM>>>(Q, Wa, Wb, Wd);
    // edge scores + softmax -> g_W (+ tail casts) (256 blocks)
    edge_kernel<<<dim3(32, Bx), 256>>>(dep, w2, wl, dst);
    // aggregation via fp16 HMMA, coalesced staging + fused residual relu
    agg_kernel<<<dim3(8, 4, Bx), 256, AGG_SMEM>>>(Q, out);
}